// round 5
// baseline (speedup 1.0000x reference)
#include <cuda_runtime.h>
#include <math.h>

// Problem dims
#define BB 8
#define SS 4096
#define DD 512
#define VV 32000
#define LL 2
#define MM (BB*SS)          // 32768 rows
#define EPSV 1e-5f

// GEMM tiling
#define BM 128
#define BN 128
#define BK 8
#define KT (DD/BK)          // 64 k-tiles

// Scratch (device globals: allocation-free)
__device__ float g_h[MM*DD];      // 64 MB  residual stream
__device__ float g_u[MM*DD];      // 64 MB  layernorm output
__device__ float g_v[MM*DD];      // 64 MB  v / states (scan in-place)
__device__ float g_abar[DD];
__device__ float g_bscale[DD];
__device__ float g_hf[BB*DD];

// ---------------------------------------------------------------------------
// Embedding gather: h[m, :] = emb[x[m], :]   (float4 vectorized)
// ---------------------------------------------------------------------------
__global__ void embed_kernel(const int* __restrict__ x, const float* __restrict__ emb) {
    int i4 = blockIdx.x * blockDim.x + threadIdx.x;   // float4 index
    int m  = i4 >> 7;                                 // DD/4 = 128 float4 per row
    int dq = i4 & 127;
    int row = x[m];
    reinterpret_cast<float4*>(g_h)[i4] =
        reinterpret_cast<const float4*>(emb + (size_t)row * DD)[dq];
}

// ---------------------------------------------------------------------------
// Per-layer scalar prep: a_bar[d], b_scale[d]
// ---------------------------------------------------------------------------
__global__ void prep_kernel(const float* __restrict__ a_log, const float* __restrict__ dt_log) {
    int d = threadIdx.x;
    float a  = -expf(a_log[d]);
    float xl = dt_log[d];
    float dt = ((xl > 20.f) ? xl : log1pf(expf(xl))) + 1e-4f;
    float half  = 0.5f * dt * a;
    float denom = 1.f - half;
    g_abar[d]   = (1.f + half) / denom;
    g_bscale[d] = dt / denom;
}

// ---------------------------------------------------------------------------
// LayerNorm: u = LN(h) * w + b.   One warp per row (D=512 -> 16 vals/lane).
// ---------------------------------------------------------------------------
__global__ void ln_kernel(const float* __restrict__ w, const float* __restrict__ b) {
    int warp = threadIdx.x >> 5, lane = threadIdx.x & 31;
    int r = blockIdx.x * 8 + warp;
    const float* xr = g_h + (size_t)r * DD;
    float xv[16];
    float s = 0.f;
#pragma unroll
    for (int j = 0; j < 16; j++) { xv[j] = xr[lane + 32*j]; s += xv[j]; }
#pragma unroll
    for (int o = 16; o > 0; o >>= 1) s += __shfl_xor_sync(0xffffffffu, s, o);
    float mu = s * (1.f/DD);
    float vr = 0.f;
#pragma unroll
    for (int j = 0; j < 16; j++) { float t = xv[j] - mu; vr += t*t; }
#pragma unroll
    for (int o = 16; o > 0; o >>= 1) vr += __shfl_xor_sync(0xffffffffu, vr, o);
    float inv = rsqrtf(vr * (1.f/DD) + EPSV);
    float* orow = g_u + (size_t)r * DD;
#pragma unroll
    for (int j = 0; j < 16; j++) {
        int c = lane + 32*j;
        orow[c] = (xv[j] - mu) * inv * w[c] + b[c];
    }
}

// ---------------------------------------------------------------------------
// Shared-memory tiled fp32 GEMM mainloop: acc += A[m0..][k] * W[n0..][k]
// A: [M, DD] row-major, W: [DD(N), DD(K)] row-major (both K-contiguous).
// 128x128x8 tiles, double-buffered, 256 threads, 8x8 micro-tile.
// ---------------------------------------------------------------------------
__device__ __forceinline__ void gemm_mainloop(
    const float* __restrict__ A, const float* __restrict__ W,
    float As[2][BK][BM], float Bs[2][BK][BN],
    int m0, int n0, float acc[8][8])
{
    int tid = threadIdx.x;
    int ldr = tid >> 1;            // tile row 0..127
    int ldq = (tid & 1) * 4;       // k sub-offset 0 or 4
    const float* aptr = A + (size_t)(m0 + ldr) * DD + ldq;
    const float* wptr = W + (size_t)(n0 + ldr) * DD + ldq;
    int tm = (tid >> 4) << 3;
    int tn = (tid & 15) << 3;

    float4 ra = *reinterpret_cast<const float4*>(aptr);
    float4 rw = *reinterpret_cast<const float4*>(wptr);
    As[0][ldq+0][ldr] = ra.x; As[0][ldq+1][ldr] = ra.y;
    As[0][ldq+2][ldr] = ra.z; As[0][ldq+3][ldr] = ra.w;
    Bs[0][ldq+0][ldr] = rw.x; Bs[0][ldq+1][ldr] = rw.y;
    Bs[0][ldq+2][ldr] = rw.z; Bs[0][ldq+3][ldr] = rw.w;
    __syncthreads();

    int buf = 0;
#pragma unroll 1
    for (int kt = 0; kt < KT; ++kt) {
        if (kt + 1 < KT) {
            ra = *reinterpret_cast<const float4*>(aptr + (kt+1)*BK);
            rw = *reinterpret_cast<const float4*>(wptr + (kt+1)*BK);
        }
#pragma unroll
        for (int kk = 0; kk < BK; ++kk) {
            float4 a0 = *reinterpret_cast<const float4*>(&As[buf][kk][tm]);
            float4 a1 = *reinterpret_cast<const float4*>(&As[buf][kk][tm+4]);
            float4 b0 = *reinterpret_cast<const float4*>(&Bs[buf][kk][tn]);
            float4 b1 = *reinterpret_cast<const float4*>(&Bs[buf][kk][tn+4]);
            float av[8] = {a0.x,a0.y,a0.z,a0.w,a1.x,a1.y,a1.z,a1.w};
            float bv[8] = {b0.x,b0.y,b0.z,b0.w,b1.x,b1.y,b1.z,b1.w};
#pragma unroll
            for (int i = 0; i < 8; i++)
#pragma unroll
                for (int j = 0; j < 8; j++)
                    acc[i][j] = fmaf(av[i], bv[j], acc[i][j]);
        }
        if (kt + 1 < KT) {
            int nb = buf ^ 1;
            As[nb][ldq+0][ldr] = ra.x; As[nb][ldq+1][ldr] = ra.y;
            As[nb][ldq+2][ldr] = ra.z; As[nb][ldq+3][ldr] = ra.w;
            Bs[nb][ldq+0][ldr] = rw.x; Bs[nb][ldq+1][ldr] = rw.y;
            Bs[nb][ldq+2][ldr] = rw.z; Bs[nb][ldq+3][ldr] = rw.w;
            __syncthreads();
            buf = nb;
        }
    }
}

// GEMM1: v[m,e] = b_scale[e] * sum_d u[m,d] * b_mat[e,d]
__global__ __launch_bounds__(256, 2) void gemm1_kernel(const float* __restrict__ Bmat) {
    __shared__ float As[2][BK][BM];
    __shared__ float Bs[2][BK][BN];
    int n0 = blockIdx.x * BN;
    int m0 = blockIdx.y * BM;
    float acc[8][8] = {};
    gemm_mainloop(g_u, Bmat, As, Bs, m0, n0, acc);

    int tm = (threadIdx.x >> 4) << 3;
    int tn = (threadIdx.x & 15) << 3;
    float4 sc0 = *reinterpret_cast<const float4*>(&g_bscale[n0 + tn]);
    float4 sc1 = *reinterpret_cast<const float4*>(&g_bscale[n0 + tn + 4]);
#pragma unroll
    for (int i = 0; i < 8; i++) {
        int m = m0 + tm + i;
        float* vp = g_v + (size_t)m * DD + n0 + tn;
        float4 o0 = make_float4(acc[i][0]*sc0.x, acc[i][1]*sc0.y, acc[i][2]*sc0.z, acc[i][3]*sc0.w);
        float4 o1 = make_float4(acc[i][4]*sc1.x, acc[i][5]*sc1.y, acc[i][6]*sc1.z, acc[i][7]*sc1.w);
        *reinterpret_cast<float4*>(vp)     = o0;
        *reinterpret_cast<float4*>(vp + 4) = o1;
    }
}

// Dual GEMM + residual: h[m,e] += sum_d st[m,d]*c[e,d] + sum_d u[m,d]*dw[e,d] + db[e]
__global__ __launch_bounds__(256, 2) void gemm_dual_kernel(
    const float* __restrict__ Cmat, const float* __restrict__ Dw,
    const float* __restrict__ db)
{
    __shared__ float As[2][BK][BM];
    __shared__ float Bs[2][BK][BN];
    int n0 = blockIdx.x * BN;
    int m0 = blockIdx.y * BM;
    float acc[8][8] = {};
    gemm_mainloop(g_v, Cmat, As, Bs, m0, n0, acc);   // states @ C^T
    __syncthreads();
    gemm_mainloop(g_u, Dw,   As, Bs, m0, n0, acc);   // u @ Dw^T

    int tm = (threadIdx.x >> 4) << 3;
    int tn = (threadIdx.x & 15) << 3;
    float4 d0 = *reinterpret_cast<const float4*>(&db[n0 + tn]);
    float4 d1 = *reinterpret_cast<const float4*>(&db[n0 + tn + 4]);
#pragma unroll
    for (int i = 0; i < 8; i++) {
        int m = m0 + tm + i;
        float* hp = g_h + (size_t)m * DD + n0 + tn;
        float4 h0 = *reinterpret_cast<const float4*>(hp);
        float4 h1 = *reinterpret_cast<const float4*>(hp + 4);
        h0.x += acc[i][0] + d0.x; h0.y += acc[i][1] + d0.y;
        h0.z += acc[i][2] + d0.z; h0.w += acc[i][3] + d0.w;
        h1.x += acc[i][4] + d1.x; h1.y += acc[i][5] + d1.y;
        h1.z += acc[i][6] + d1.z; h1.w += acc[i][7] + d1.w;
        *reinterpret_cast<float4*>(hp)     = h0;
        *reinterpret_cast<float4*>(hp + 4) = h1;
    }
}

// ---------------------------------------------------------------------------
// Diagonal recurrence, in-place over g_v: st = st*abar[d] + v; v := st
// One thread per (b,d) channel; unroll-8 load batching for MLP.
// ---------------------------------------------------------------------------
__global__ void scan_kernel() {
    int t = blockIdx.x * blockDim.x + threadIdx.x;  // 0..4095
    int b = t >> 9;
    int d = t & (DD - 1);
    float ab = g_abar[d];
    float st = 0.f;
    float* p = g_v + (size_t)b * SS * DD + d;
#pragma unroll 1
    for (int s0 = 0; s0 < SS; s0 += 8) {
        float vb[8];
#pragma unroll
        for (int i = 0; i < 8; i++) vb[i] = p[(size_t)(s0 + i) * DD];
#pragma unroll
        for (int i = 0; i < 8; i++) {
            st = fmaf(st, ab, vb[i]);
            p[(size_t)(s0 + i) * DD] = st;
        }
    }
}

// ---------------------------------------------------------------------------
// Final LN on last timestep of each batch row -> g_hf
// ---------------------------------------------------------------------------
__global__ void final_ln_kernel(const float* __restrict__ fw, const float* __restrict__ fb) {
    int warp = threadIdx.x >> 5, lane = threadIdx.x & 31;   // 8 warps = 8 batch rows
    const float* xr = g_h + ((size_t)warp * SS + (SS - 1)) * DD;
    float xv[16];
    float s = 0.f;
#pragma unroll
    for (int j = 0; j < 16; j++) { xv[j] = xr[lane + 32*j]; s += xv[j]; }
#pragma unroll
    for (int o = 16; o > 0; o >>= 1) s += __shfl_xor_sync(0xffffffffu, s, o);
    float mu = s * (1.f/DD);
    float vr = 0.f;
#pragma unroll
    for (int j = 0; j < 16; j++) { float tt = xv[j] - mu; vr += tt*tt; }
#pragma unroll
    for (int o = 16; o > 0; o >>= 1) vr += __shfl_xor_sync(0xffffffffu, vr, o);
    float inv = rsqrtf(vr * (1.f/DD) + EPSV);
#pragma unroll
    for (int j = 0; j < 16; j++) {
        int c = lane + 32*j;
        g_hf[warp*DD + c] = (xv[j] - mu) * inv * fw[c] + fb[c];
    }
}

// ---------------------------------------------------------------------------
// Output: out[b,v] = hf[b,:] . out_w[v,:] + out_b[v].  Warp per vocab row.
// ---------------------------------------------------------------------------
__global__ __launch_bounds__(256) void out_kernel(
    const float* __restrict__ Wout, const float* __restrict__ bout, float* __restrict__ out)
{
    __shared__ float hf[BB][DD];
    for (int i = threadIdx.x; i < BB*DD; i += 256) hf[i >> 9][i & 511] = g_hf[i];
    __syncthreads();

    int warp = threadIdx.x >> 5, lane = threadIdx.x & 31;
    int v = blockIdx.x * 8 + warp;
    const float* wr = Wout + (size_t)v * DD;
    float ow[16];
#pragma unroll
    for (int j = 0; j < 16; j++) ow[j] = wr[lane + 32*j];
    float res[BB];
#pragma unroll
    for (int b = 0; b < BB; b++) {
        float s = 0.f;
#pragma unroll
        for (int j = 0; j < 16; j++) s = fmaf(ow[j], hf[b][lane + 32*j], s);
#pragma unroll
        for (int o = 16; o > 0; o >>= 1) s += __shfl_xor_sync(0xffffffffu, s, o);
        res[b] = s;
    }
    if (lane == 0) {
        float bb = bout[v];
#pragma unroll
        for (int b = 0; b < BB; b++) out[(size_t)b * VV + v] = res[b] + bb;
    }
}

// ---------------------------------------------------------------------------
extern "C" void kernel_launch(void* const* d_in, const int* in_sizes, int n_in,
                              void* d_out, int out_size)
{
    const int*   x      = (const int*)  d_in[0];
    const float* emb    = (const float*)d_in[1];
    const float* norm_w = (const float*)d_in[2];
    const float* norm_b = (const float*)d_in[3];
    const float* b_mat  = (const float*)d_in[4];
    const float* c_mat  = (const float*)d_in[5];
    const float* d_wm   = (const float*)d_in[6];
    const float* d_bv   = (const float*)d_in[7];
    const float* a_log  = (const float*)d_in[8];
    const float* dt_log = (const float*)d_in[9];
    const float* fn_w   = (const float*)d_in[10];
    const float* fn_b   = (const float*)d_in[11];
    const float* out_w  = (const float*)d_in[12];
    const float* out_b  = (const float*)d_in[13];
    float* out = (float*)d_out;

    embed_kernel<<<(MM * DD / 4) / 256, 256>>>(x, emb);

    dim3 ggrid(DD / BN, MM / BM);   // (4, 256)
    for (int l = 0; l < LL; l++) {
        prep_kernel<<<1, DD>>>(a_log + l*DD, dt_log + l*DD);
        ln_kernel<<<MM / 8, 256>>>(norm_w + l*DD, norm_b + l*DD);
        gemm1_kernel<<<ggrid, 256>>>(b_mat + (size_t)l*DD*DD);
        scan_kernel<<<16, 256>>>();
        gemm_dual_kernel<<<ggrid, 256>>>(c_mat + (size_t)l*DD*DD,
                                         d_wm + (size_t)l*DD*DD,
                                         d_bv + l*DD);
    }
    final_ln_kernel<<<1, 256>>>(fn_w, fn_b);
    out_kernel<<<VV / 8, 256>>>(out_w, out_b, out);
}